// round 13
// baseline (speedup 1.0000x reference)
#include <cuda_runtime.h>

#define B_TOTAL   1024
#define T_STEPS   512
#define NGATE     256
#define NCTA      148
#define NCTA7     136      /* 136 CTAs * 7 + 12 CTAs * 6 = 1024 */
#define NTHREADS  384
#define HSTRIDE   68

typedef unsigned long long u64;

__device__ __forceinline__ u64 ffma2(u64 a, u64 b, u64 c) {
    u64 d;
    asm("fma.rn.f32x2 %0, %1, %2, %3;" : "=l"(d) : "l"(a), "l"(b), "l"(c));
    return d;
}
__device__ __forceinline__ float hadd2(u64 v) {
    float lo, hi;
    asm("mov.b64 {%0, %1}, %2;" : "=f"(lo), "=f"(hi) : "l"(v));
    return lo + hi;
}
__device__ __forceinline__ float tanh_apx(float x) {
    float y;
    asm("tanh.approx.f32 %0, %1;" : "=f"(y) : "f"(x));
    return y;
}
__device__ __forceinline__ float sig_apx(float x) {
    return fmaf(0.5f, tanh_apx(0.5f * x), 0.5f);
}

#define BAR_SYNC(id, cnt)   asm volatile("bar.sync %0, %1;"   :: "r"(id), "r"(cnt) : "memory")
#define BAR_ARRIVE(id, cnt) asm volatile("bar.arrive %0, %1;" :: "r"(id), "r"(cnt) : "memory")
// ids: 0=__syncthreads, 1/2=FULL[slot](256: delta arrive + beta sync),
//      3/4=EMPTY[slot](256: beta arrive + delta sync), 5=gamma+delta(256), 6=beta(128)

// All three weight matrices share one quad transform:
//   d = (row>>6)*1024 + kc*128 + khalf*64 + (row&63)
// so a lane (half, s) reading block j gets row j*64+s, k-half 'half' -> the 4
// blocks j=0..3 are exactly gates i,f,g,o of cell u=s. Conflict-free LDS.128.
//
// SMEM (bytes):
//  wq    [0, 196608): whh0 [0,4096) | wih1 [4096,8192) | whh1 [8192,12288) quads
//  g1a   [196608): f32 ring, 2 slots x [7 b][256 g]
//  h0    [210944): f32 2 slots x [7 b][68]  (double-buffered; half1 at +36 floats)
//  h1    [214752): f32 [7 b][68]
//  wfc   [216656): f32 [64]
#define SM_W      0
#define SM_G1A    196608
#define SM_H0     210944
#define SM_H1     214752
#define SM_WFC    216656
#define SMEM_BYTES 216960
#define G1A_SLOT  1792
#define H0_SLOT   476

template<int NBT>
__device__ __forceinline__ void lstm_body(
    int bbase, const float* __restrict__ x,
    const float* __restrict__ W_ih0,
    const float* __restrict__ b_ih0, const float* __restrict__ b_hh0,
    const float* __restrict__ b_ih1, const float* __restrict__ b_hh1,
    const float* __restrict__ b_fc, float* __restrict__ out,
    ulonglong2* wq, float* g1a_s, float* h0_s, float* h1_s, float* wfc_s)
{
    const int tid  = threadIdx.x;
    const int lane = tid & 31;
    const int half = lane >> 4;
    const int hofs = half * 36;
    const int wid  = tid >> 5;

    for (int i = tid; i < 2 * H0_SLOT; i += NTHREADS) h0_s[i] = 0.0f;
    for (int i = tid; i < H0_SLOT;     i += NTHREADS) h1_s[i] = 0.0f;
    __syncthreads();   // weights + zeros visible

    if (tid < 128) {
        // ============ GAMMA: whh0 (4 gate rows of cell u=s) ; act0 in regs ============
        const int s    = (wid & 3) * 16 + (lane & 15);    // u = s
        const int pads = (s >> 5) << 2;
        const int bo   = half ? 4 : 0;
        const int nOwn = half ? (NBT - 4) : 4;
        const float bI = b_ih0[s]        + b_hh0[s];
        const float bF = b_ih0[64 + s]   + b_hh0[64 + s];
        const float bG = b_ih0[128 + s]  + b_hh0[128 + s];
        const float bO = b_ih0[192 + s]  + b_hh0[192 + s];
        const float wxi = W_ih0[s];
        const float wxf = W_ih0[64 + s];
        const float wxg = W_ih0[128 + s];
        const float wxo = W_ih0[192 + s];
        const float* xr[4];
#pragma unroll
        for (int j = 0; j < 4; j++) xr[j] = x + (size_t)(bbase + bo + j) * T_STEPS;
        float cG[4] = {0.0f, 0.0f, 0.0f, 0.0f};

        // prologue: h0(0) from gates = b0 + wx*x(0)   -> slot 0
#pragma unroll
        for (int j = 0; j < 4; j++) {
            if (j < nOwn) {
                float xv = __ldg(xr[j]);
                float ii = sig_apx(fmaf(wxi, xv, bI));
                float ff = sig_apx(fmaf(wxf, xv, bF));
                float gv = tanh_apx(fmaf(wxg, xv, bG));
                float oo = sig_apx(fmaf(wxo, xv, bO));
                cG[j] = ii * gv;
                h0_s[(bo + j) * HSTRIDE + s + pads] = oo * tanh_apx(cG[j]);
                (void)ff;
            }
        }
        BAR_SYNC(5, 256);

        for (int t = 0; t < T_STEPS - 1; t++) {
            const float* h0r = h0_s + (t & 1) * H0_SLOT;
            float*       h0w = h0_s + ((t + 1) & 1) * H0_SLOT;

            u64 aI[NBT], aF[NBT], aG[NBT], aO[NBT];
#pragma unroll
            for (int b = 0; b < NBT; b++) { aI[b]=0ull; aF[b]=0ull; aG[b]=0ull; aO[b]=0ull; }
#pragma unroll
            for (int kc = 0; kc < 8; kc++) {
                const int wix = kc * 128 + half * 64 + s;
                ulonglong2 wI = wq[       wix];
                ulonglong2 wF = wq[1024 + wix];
                ulonglong2 wG = wq[2048 + wix];
                ulonglong2 wO = wq[3072 + wix];
#pragma unroll
                for (int b = 0; b < NBT; b++) {
                    ulonglong2 h2 = *(const ulonglong2*)(h0r + b * HSTRIDE + hofs + kc * 4);
                    aI[b] = ffma2(wI.x, h2.x, aI[b]); aI[b] = ffma2(wI.y, h2.y, aI[b]);
                    aF[b] = ffma2(wF.x, h2.x, aF[b]); aF[b] = ffma2(wF.y, h2.y, aF[b]);
                    aG[b] = ffma2(wG.x, h2.x, aG[b]); aG[b] = ffma2(wG.y, h2.y, aG[b]);
                    aO[b] = ffma2(wO.x, h2.x, aO[b]); aO[b] = ffma2(wO.y, h2.y, aO[b]);
                }
            }
            float sI[4], sF[4], sG[4], sO[4];
#pragma unroll
            for (int b = 0; b < NBT; b++) {
                float vI = hadd2(aI[b]); vI += __shfl_xor_sync(0xffffffffu, vI, 16);
                float vF = hadd2(aF[b]); vF += __shfl_xor_sync(0xffffffffu, vF, 16);
                float vG = hadd2(aG[b]); vG += __shfl_xor_sync(0xffffffffu, vG, 16);
                float vO = hadd2(aO[b]); vO += __shfl_xor_sync(0xffffffffu, vO, 16);
                if (b < 4) { if (!half) { sI[b]=vI; sF[b]=vF; sG[b]=vG; sO[b]=vO; } }
                else       { if ( half) { sI[b-4]=vI; sF[b-4]=vF; sG[b-4]=vG; sO[b-4]=vO; } }
            }
            // act0(t+1) entirely from registers
#pragma unroll
            for (int j = 0; j < 4; j++) {
                if (j < nOwn) {
                    float xv = __ldg(xr[j] + t + 1);
                    float ii = sig_apx(fmaf(wxi, xv, sI[j] + bI));
                    float ff = sig_apx(fmaf(wxf, xv, sF[j] + bF));
                    float gv = tanh_apx(fmaf(wxg, xv, sG[j] + bG));
                    float oo = sig_apx(fmaf(wxo, xv, sO[j] + bO));
                    cG[j] = ff * cG[j] + ii * gv;
                    h0w[(bo + j) * HSTRIDE + s + pads] = oo * tanh_apx(cG[j]);
                }
            }
            BAR_SYNC(5, 256);   // h0(t+1) visible to gamma+delta
        }
    } else if (tid < 256) {
        // ============ DELTA: wih1 (4 gate rows of cell u=sd) -> g1a ============
        const int sd   = ((wid - 4) & 3) * 16 + (lane & 15);
        const int bo   = half ? 4 : 0;
        const int nOwn = half ? (NBT - 4) : 4;
        const float bI = b_ih1[sd]       + b_hh1[sd];
        const float bF = b_ih1[64 + sd]  + b_hh1[64 + sd];
        const float bG = b_ih1[128 + sd] + b_hh1[128 + sd];
        const float bO = b_ih1[192 + sd] + b_hh1[192 + sd];

        BAR_SYNC(5, 256);   // wait h0(0)

        for (int t = 0; t < T_STEPS; t++) {
            if (t >= 2) BAR_SYNC(3 + (t & 1), 256);       // EMPTY: g1a slot reusable
            const float* h0r = h0_s + (t & 1) * H0_SLOT;

            u64 aI[NBT], aF[NBT], aG[NBT], aO[NBT];
#pragma unroll
            for (int b = 0; b < NBT; b++) { aI[b]=0ull; aF[b]=0ull; aG[b]=0ull; aO[b]=0ull; }
#pragma unroll
            for (int kc = 0; kc < 8; kc++) {
                const int wix = 4096 + kc * 128 + half * 64 + sd;
                ulonglong2 wI = wq[       wix];
                ulonglong2 wF = wq[1024 + wix];
                ulonglong2 wG = wq[2048 + wix];
                ulonglong2 wO = wq[3072 + wix];
#pragma unroll
                for (int b = 0; b < NBT; b++) {
                    ulonglong2 h2 = *(const ulonglong2*)(h0r + b * HSTRIDE + hofs + kc * 4);
                    aI[b] = ffma2(wI.x, h2.x, aI[b]); aI[b] = ffma2(wI.y, h2.y, aI[b]);
                    aF[b] = ffma2(wF.x, h2.x, aF[b]); aF[b] = ffma2(wF.y, h2.y, aF[b]);
                    aG[b] = ffma2(wG.x, h2.x, aG[b]); aG[b] = ffma2(wG.y, h2.y, aG[b]);
                    aO[b] = ffma2(wO.x, h2.x, aO[b]); aO[b] = ffma2(wO.y, h2.y, aO[b]);
                }
            }
            float sI[4], sF[4], sG[4], sO[4];
#pragma unroll
            for (int b = 0; b < NBT; b++) {
                float vI = hadd2(aI[b]); vI += __shfl_xor_sync(0xffffffffu, vI, 16);
                float vF = hadd2(aF[b]); vF += __shfl_xor_sync(0xffffffffu, vF, 16);
                float vG = hadd2(aG[b]); vG += __shfl_xor_sync(0xffffffffu, vG, 16);
                float vO = hadd2(aO[b]); vO += __shfl_xor_sync(0xffffffffu, vO, 16);
                if (b < 4) { if (!half) { sI[b]=vI; sF[b]=vF; sG[b]=vG; sO[b]=vO; } }
                else       { if ( half) { sI[b-4]=vI; sF[b-4]=vF; sG[b-4]=vG; sO[b-4]=vO; } }
            }
            float* g1a = g1a_s + (t & 1) * G1A_SLOT;
#pragma unroll
            for (int j = 0; j < 4; j++) {
                if (j < nOwn) {
                    int base = (bo + j) * NGATE + sd;
                    g1a[base]       = sI[j] + bI;
                    g1a[base + 64]  = sF[j] + bF;
                    g1a[base + 128] = sG[j] + bG;
                    g1a[base + 192] = sO[j] + bO;
                }
            }
            BAR_ARRIVE(1 + (t & 1), 256);                 // FULL: g1a(t) -> beta
            if (t < T_STEPS - 1) BAR_SYNC(5, 256);        // h0(t+1) ready
        }
    } else {
        // ============ BETA: whh1 ; act1 (register partials, round-12 style) ============
        const int sb    = ((wid - 8) & 3) * 16 + (lane & 15);
        const int padB  = (sb >> 5) << 2;
        const int nJ    = half ? (NBT - 4) : 4;
        const int boB   = half ? 4 : 0;

        float sg0[4], sg1[4], sg2[4], sg3[4];
        float cS[4] = {0.0f, 0.0f, 0.0f, 0.0f};

        for (int t = 0; t < T_STEPS; t++) {
            u64 aC0[NBT], aC1[NBT], aC2[NBT], aC3[NBT];
#pragma unroll
            for (int b = 0; b < NBT; b++) { aC0[b]=0ull; aC1[b]=0ull; aC2[b]=0ull; aC3[b]=0ull; }
#pragma unroll
            for (int kc = 0; kc < 8; kc++) {
                const int wix = 8192 + kc * 128 + half * 64 + sb;
                ulonglong2 wc0 = wq[       wix];
                ulonglong2 wc1 = wq[1024 + wix];
                ulonglong2 wc2 = wq[2048 + wix];
                ulonglong2 wc3 = wq[3072 + wix];
#pragma unroll
                for (int b = 0; b < NBT; b++) {
                    ulonglong2 h2 = *(const ulonglong2*)(h1_s + b * HSTRIDE + hofs + kc * 4);
                    aC0[b] = ffma2(wc0.x, h2.x, aC0[b]); aC0[b] = ffma2(wc0.y, h2.y, aC0[b]);
                    aC1[b] = ffma2(wc1.x, h2.x, aC1[b]); aC1[b] = ffma2(wc1.y, h2.y, aC1[b]);
                    aC2[b] = ffma2(wc2.x, h2.x, aC2[b]); aC2[b] = ffma2(wc2.y, h2.y, aC2[b]);
                    aC3[b] = ffma2(wc3.x, h2.x, aC3[b]); aC3[b] = ffma2(wc3.y, h2.y, aC3[b]);
                }
            }
#pragma unroll
            for (int b = 0; b < NBT; b++) {
                float s0 = hadd2(aC0[b]); s0 += __shfl_xor_sync(0xffffffffu, s0, 16);
                float s1 = hadd2(aC1[b]); s1 += __shfl_xor_sync(0xffffffffu, s1, 16);
                float s2 = hadd2(aC2[b]); s2 += __shfl_xor_sync(0xffffffffu, s2, 16);
                float s3 = hadd2(aC3[b]); s3 += __shfl_xor_sync(0xffffffffu, s3, 16);
                if (b < 4) { if (!half) { sg0[b]=s0; sg1[b]=s1; sg2[b]=s2; sg3[b]=s3; } }
                else       { if ( half) { sg0[b-4]=s0; sg1[b-4]=s1; sg2[b-4]=s2; sg3[b-4]=s3; } }
            }

            BAR_SYNC(1 + (t & 1), 256);                   // FULL: g1a(t) ready
            const float* g1a = g1a_s + (t & 1) * G1A_SLOT;

#pragma unroll
            for (int j = 0; j < 4; j++) {
                if (j < nJ) {
                    int b  = boB + j;
                    int gi = b * NGATE + sb;
                    float p0 = sg0[j] + g1a[gi];
                    float p1 = sg1[j] + g1a[gi + 64];
                    float p2 = sg2[j] + g1a[gi + 128];
                    float p3 = sg3[j] + g1a[gi + 192];
                    float ii = sig_apx(p0), ff = sig_apx(p1), gv = tanh_apx(p2), oo = sig_apx(p3);
                    cS[j] = ff * cS[j] + ii * gv;
                    h1_s[b * HSTRIDE + sb + padB] = oo * tanh_apx(cS[j]);
                }
            }

            if (t < T_STEPS - 2) BAR_ARRIVE(3 + (t & 1), 256);   // EMPTY
            if (t < T_STEPS - 1) BAR_SYNC(6, 128);               // h1(t) visible
        }
    }
    __syncthreads();

    // ---- output FC: h0 final lives in slot (T_STEPS-1)&1 = 1 ----
    if (tid < 2 * NBT) {
        int b = (tid < NBT) ? tid : tid - NBT;
        const float* hp = (tid < NBT) ? (h0_s + ((T_STEPS - 1) & 1) * H0_SLOT) : h1_s;
        float s = b_fc[0];
#pragma unroll
        for (int uu = 0; uu < 64; uu++)
            s = fmaf(hp[b * HSTRIDE + uu + ((uu >> 5) << 2)], wfc_s[uu], s);
        out[(tid < NBT ? 0 : B_TOTAL) + bbase + b] = s;
    }
}

__global__ void __launch_bounds__(NTHREADS, 1)
lstm2_kernel(const float* __restrict__ x,
             const float* __restrict__ W_ih0, const float* __restrict__ W_hh0,
             const float* __restrict__ b_ih0, const float* __restrict__ b_hh0,
             const float* __restrict__ W_ih1, const float* __restrict__ W_hh1,
             const float* __restrict__ b_ih1, const float* __restrict__ b_hh1,
             const float* __restrict__ W_fc,  const float* __restrict__ b_fc,
             float* __restrict__ out)
{
    extern __shared__ char smem[];
    ulonglong2* wq = (ulonglong2*)(smem + SM_W);
    float* g1a_s = (float*)(smem + SM_G1A);
    float* h0_s  = (float*)(smem + SM_H0);
    float* h1_s  = (float*)(smem + SM_H1);
    float* wfc_s = (float*)(smem + SM_WFC);

    const int tid = threadIdx.x;

    // upload all three matrices with the shared gate-block quad transform
    for (int idx = tid; idx < 4096; idx += NTHREADS) {
        int row = idx >> 4, q = idx & 15;
        int hh = q >> 3, kc = q & 7;
        int d = (row >> 6) * 1024 + kc * 128 + hh * 64 + (row & 63);
        wq[d]        = ((const ulonglong2*)W_hh0)[idx];
        wq[4096 + d] = ((const ulonglong2*)W_ih1)[idx];
        wq[8192 + d] = ((const ulonglong2*)W_hh1)[idx];
    }
    if (tid < 64) wfc_s[tid] = W_fc[tid];

    if (blockIdx.x < NCTA7) {
        lstm_body<7>(blockIdx.x * 7, x, W_ih0, b_ih0, b_hh0, b_ih1, b_hh1,
                     b_fc, out, wq, g1a_s, h0_s, h1_s, wfc_s);
    } else {
        lstm_body<6>(NCTA7 * 7 + (blockIdx.x - NCTA7) * 6, x, W_ih0, b_ih0, b_hh0,
                     b_ih1, b_hh1, b_fc, out, wq, g1a_s, h0_s, h1_s, wfc_s);
    }
}

extern "C" void kernel_launch(void* const* d_in, const int* in_sizes, int n_in,
                              void* d_out, int out_size) {
    const float* x     = (const float*)d_in[0];
    const float* W_ih0 = (const float*)d_in[1];
    const float* W_hh0 = (const float*)d_in[2];
    const float* b_ih0 = (const float*)d_in[3];
    const float* b_hh0 = (const float*)d_in[4];
    const float* W_ih1 = (const float*)d_in[5];
    const float* W_hh1 = (const float*)d_in[6];
    const float* b_ih1 = (const float*)d_in[7];
    const float* b_hh1 = (const float*)d_in[8];
    const float* W_fc  = (const float*)d_in[9];
    const float* b_fc  = (const float*)d_in[10];
    float* out = (float*)d_out;

    cudaFuncSetAttribute(lstm2_kernel,
                         cudaFuncAttributeMaxDynamicSharedMemorySize, SMEM_BYTES);
    lstm2_kernel<<<NCTA, NTHREADS, SMEM_BYTES>>>(
        x, W_ih0, W_hh0, b_ih0, b_hh0,
        W_ih1, W_hh1, b_ih1, b_hh1, W_fc, b_fc, out);
}

// round 14
// speedup vs baseline: 1.0111x; 1.0111x over previous
#include <cuda_runtime.h>

#define B_TOTAL   1024
#define T_STEPS   512
#define NGATE     256
#define NCTA      148
#define NCTA7     136      /* 136 CTAs * 7 + 12 CTAs * 6 = 1024 */
#define NTHREADS  384
#define HSTRIDE   68

typedef unsigned long long u64;

__device__ __forceinline__ u64 ffma2(u64 a, u64 b, u64 c) {
    u64 d;
    asm("fma.rn.f32x2 %0, %1, %2, %3;" : "=l"(d) : "l"(a), "l"(b), "l"(c));
    return d;
}
__device__ __forceinline__ float hadd2(u64 v) {
    float lo, hi;
    asm("mov.b64 {%0, %1}, %2;" : "=f"(lo), "=f"(hi) : "l"(v));
    return lo + hi;
}
__device__ __forceinline__ float tanh_apx(float x) {
    float y;
    asm("tanh.approx.f32 %0, %1;" : "=f"(y) : "f"(x));
    return y;
}
__device__ __forceinline__ float sig_apx(float x) {
    return fmaf(0.5f, tanh_apx(0.5f * x), 0.5f);
}

#define BAR_SYNC(id, cnt)   asm volatile("bar.sync %0, %1;"   :: "r"(id), "r"(cnt) : "memory")
#define BAR_ARRIVE(id, cnt) asm volatile("bar.arrive %0, %1;" :: "r"(id), "r"(cnt) : "memory")
// ids: 0=__syncthreads(384)
//      1/2 = G1FULL[slot]  (delta arrive 128 + beta sync 128)  = 256
//      3/4 = G1EMPTY[slot] (beta arrive 128 + delta sync 128)  = 256
//      8/9 = H0FULL[slot]  (gamma arrive 128 + delta sync 128) = 256
//     10/11= H0EMPTY[slot] (delta arrive 128 + gamma sync 128) = 256
//      6   = beta internal (128), 7 = gamma internal (128)

// Weight quad transform (same for all 3 matrices):
//   d = (row>>6)*1024 + kc*128 + khalf*64 + (row&63)
// lane (half,s) reading block j gets gate-j row of cell u=s. Conflict-free LDS.128.
//
// SMEM (bytes):
//  wq    [0,196608): whh0 | wih1(+4096q) | whh1(+8192q)
//  g1a   [196608): f32 ring 2 x [7 b][256 g]
//  h0    [210944): f32 ring 2 x [7 b][68]
//  h1    [214752): f32 [7 b][68]
//  wfc   [216656): f32 [64]
#define SM_W      0
#define SM_G1A    196608
#define SM_H0     210944
#define SM_H1     214752
#define SM_WFC    216656
#define SMEM_BYTES 216960
#define G1A_SLOT  1792
#define H0_SLOT   476

template<int NBT>
__device__ __forceinline__ void lstm_body(
    int bbase, const float* __restrict__ x,
    const float* __restrict__ W_ih0,
    const float* __restrict__ b_ih0, const float* __restrict__ b_hh0,
    const float* __restrict__ b_ih1, const float* __restrict__ b_hh1,
    const float* __restrict__ b_fc, float* __restrict__ out,
    ulonglong2* wq, float* g1a_s, float* h0_s, float* h1_s, float* wfc_s)
{
    const int tid  = threadIdx.x;
    const int lane = tid & 31;
    const int half = lane >> 4;
    const int hofs = half * 36;
    const int wid  = tid >> 5;
    const int s    = (wid & 3) * 16 + (lane & 15);   // owned cell u within group
    const int pads = (s >> 5) << 2;
    const int bo   = half ? 4 : 0;
    const int nOwn = half ? (NBT - 4) : 4;

    for (int i = tid; i < 2 * H0_SLOT; i += NTHREADS) h0_s[i] = 0.0f;
    for (int i = tid; i < H0_SLOT;     i += NTHREADS) h1_s[i] = 0.0f;
    __syncthreads();   // weights + zeros visible

    if (tid >= 256) {
        // ============ GAMMA (warps 8-11, highest priority): whh0 ; act0 in regs ============
        const float bI = b_ih0[s]        + b_hh0[s];
        const float bF = b_ih0[64 + s]   + b_hh0[64 + s];
        const float bG = b_ih0[128 + s]  + b_hh0[128 + s];
        const float bO = b_ih0[192 + s]  + b_hh0[192 + s];
        const float wxi = W_ih0[s];
        const float wxf = W_ih0[64 + s];
        const float wxg = W_ih0[128 + s];
        const float wxo = W_ih0[192 + s];
        const float* xr[4];
#pragma unroll
        for (int j = 0; j < 4; j++) xr[j] = x + (size_t)(bbase + bo + j) * T_STEPS;
        float cG[4] = {0.0f, 0.0f, 0.0f, 0.0f};

        // prologue: h0(0) -> slot 0, publish
#pragma unroll
        for (int j = 0; j < 4; j++) {
            if (j < nOwn) {
                float xv = __ldg(xr[j]);
                float ii = sig_apx(fmaf(wxi, xv, bI));
                float gv = tanh_apx(fmaf(wxg, xv, bG));
                float oo = sig_apx(fmaf(wxo, xv, bO));
                cG[j] = ii * gv;
                h0_s[(bo + j) * HSTRIDE + s + pads] = oo * tanh_apx(cG[j]);
            }
        }
        BAR_SYNC(7, 128);
        BAR_ARRIVE(8, 256);                    // H0FULL[0]

        for (int t = 0; t < T_STEPS - 1; t++) {
            const float* h0r = h0_s + (t & 1) * H0_SLOT;
            float*       h0w = h0_s + ((t + 1) & 1) * H0_SLOT;

            u64 aI[NBT], aF[NBT], aG[NBT], aO[NBT];
#pragma unroll
            for (int b = 0; b < NBT; b++) { aI[b]=0ull; aF[b]=0ull; aG[b]=0ull; aO[b]=0ull; }
#pragma unroll
            for (int kc = 0; kc < 8; kc++) {
                const int wix = kc * 128 + half * 64 + s;
                ulonglong2 wI = wq[       wix];
                ulonglong2 wF = wq[1024 + wix];
                ulonglong2 wG = wq[2048 + wix];
                ulonglong2 wO = wq[3072 + wix];
#pragma unroll
                for (int b = 0; b < NBT; b++) {
                    ulonglong2 h2 = *(const ulonglong2*)(h0r + b * HSTRIDE + hofs + kc * 4);
                    aI[b] = ffma2(wI.x, h2.x, aI[b]); aI[b] = ffma2(wI.y, h2.y, aI[b]);
                    aF[b] = ffma2(wF.x, h2.x, aF[b]); aF[b] = ffma2(wF.y, h2.y, aF[b]);
                    aG[b] = ffma2(wG.x, h2.x, aG[b]); aG[b] = ffma2(wG.y, h2.y, aG[b]);
                    aO[b] = ffma2(wO.x, h2.x, aO[b]); aO[b] = ffma2(wO.y, h2.y, aO[b]);
                }
            }
            float sI[4], sF[4], sG[4], sO[4];
#pragma unroll
            for (int b = 0; b < NBT; b++) {
                float vI = hadd2(aI[b]); vI += __shfl_xor_sync(0xffffffffu, vI, 16);
                float vF = hadd2(aF[b]); vF += __shfl_xor_sync(0xffffffffu, vF, 16);
                float vG = hadd2(aG[b]); vG += __shfl_xor_sync(0xffffffffu, vG, 16);
                float vO = hadd2(aO[b]); vO += __shfl_xor_sync(0xffffffffu, vO, 16);
                if (b < 4) { if (!half) { sI[b]=vI; sF[b]=vF; sG[b]=vG; sO[b]=vO; } }
                else       { if ( half) { sI[b-4]=vI; sF[b-4]=vF; sG[b-4]=vG; sO[b-4]=vO; } }
            }
            if (t >= 1) BAR_SYNC(10 + ((t + 1) & 1), 256);   // H0EMPTY: write slot reusable
            // act0(t+1) from registers
#pragma unroll
            for (int j = 0; j < 4; j++) {
                if (j < nOwn) {
                    float xv = __ldg(xr[j] + t + 1);
                    float ii = sig_apx(fmaf(wxi, xv, sI[j] + bI));
                    float ff = sig_apx(fmaf(wxf, xv, sF[j] + bF));
                    float gv = tanh_apx(fmaf(wxg, xv, sG[j] + bG));
                    float oo = sig_apx(fmaf(wxo, xv, sO[j] + bO));
                    cG[j] = ff * cG[j] + ii * gv;
                    h0w[(bo + j) * HSTRIDE + s + pads] = oo * tanh_apx(cG[j]);
                }
            }
            BAR_SYNC(7, 128);                          // gamma visibility of h0(t+1)
            BAR_ARRIVE(8 + ((t + 1) & 1), 256);        // H0FULL[(t+1)&1]
        }
    } else if (tid < 128) {
        // ============ DELTA (warps 0-3, lowest priority): wih1 -> g1a ============
        const float bI = b_ih1[s]        + b_hh1[s];
        const float bF = b_ih1[64 + s]   + b_hh1[64 + s];
        const float bG = b_ih1[128 + s]  + b_hh1[128 + s];
        const float bO = b_ih1[192 + s]  + b_hh1[192 + s];

        for (int t = 0; t < T_STEPS; t++) {
            BAR_SYNC(8 + (t & 1), 256);                // H0FULL: h0(t) ready
            if (t >= 2) BAR_SYNC(3 + (t & 1), 256);    // G1EMPTY: g1a slot reusable
            const float* h0r = h0_s + (t & 1) * H0_SLOT;

            u64 aI[NBT], aF[NBT], aG[NBT], aO[NBT];
#pragma unroll
            for (int b = 0; b < NBT; b++) { aI[b]=0ull; aF[b]=0ull; aG[b]=0ull; aO[b]=0ull; }
#pragma unroll
            for (int kc = 0; kc < 8; kc++) {
                const int wix = 4096 + kc * 128 + half * 64 + s;
                ulonglong2 wI = wq[       wix];
                ulonglong2 wF = wq[1024 + wix];
                ulonglong2 wG = wq[2048 + wix];
                ulonglong2 wO = wq[3072 + wix];
#pragma unroll
                for (int b = 0; b < NBT; b++) {
                    ulonglong2 h2 = *(const ulonglong2*)(h0r + b * HSTRIDE + hofs + kc * 4);
                    aI[b] = ffma2(wI.x, h2.x, aI[b]); aI[b] = ffma2(wI.y, h2.y, aI[b]);
                    aF[b] = ffma2(wF.x, h2.x, aF[b]); aF[b] = ffma2(wF.y, h2.y, aF[b]);
                    aG[b] = ffma2(wG.x, h2.x, aG[b]); aG[b] = ffma2(wG.y, h2.y, aG[b]);
                    aO[b] = ffma2(wO.x, h2.x, aO[b]); aO[b] = ffma2(wO.y, h2.y, aO[b]);
                }
            }
            float sI[4], sF[4], sG[4], sO[4];
#pragma unroll
            for (int b = 0; b < NBT; b++) {
                float vI = hadd2(aI[b]); vI += __shfl_xor_sync(0xffffffffu, vI, 16);
                float vF = hadd2(aF[b]); vF += __shfl_xor_sync(0xffffffffu, vF, 16);
                float vG = hadd2(aG[b]); vG += __shfl_xor_sync(0xffffffffu, vG, 16);
                float vO = hadd2(aO[b]); vO += __shfl_xor_sync(0xffffffffu, vO, 16);
                if (b < 4) { if (!half) { sI[b]=vI; sF[b]=vF; sG[b]=vG; sO[b]=vO; } }
                else       { if ( half) { sI[b-4]=vI; sF[b-4]=vF; sG[b-4]=vG; sO[b-4]=vO; } }
            }
            BAR_ARRIVE(10 + (t & 1), 256);             // H0EMPTY: done reading h0(t)

            float* g1a = g1a_s + (t & 1) * G1A_SLOT;
#pragma unroll
            for (int j = 0; j < 4; j++) {
                if (j < nOwn) {
                    int base = (bo + j) * NGATE + s;
                    g1a[base]       = sI[j] + bI;
                    g1a[base + 64]  = sF[j] + bF;
                    g1a[base + 128] = sG[j] + bG;
                    g1a[base + 192] = sO[j] + bO;
                }
            }
            BAR_ARRIVE(1 + (t & 1), 256);              // G1FULL: g1a(t) -> beta
        }
    } else {
        // ============ BETA (warps 4-7): whh1 ; act1 in regs ============
        float sg0[4], sg1[4], sg2[4], sg3[4];
        float cS[4] = {0.0f, 0.0f, 0.0f, 0.0f};

        for (int t = 0; t < T_STEPS; t++) {
            u64 aC0[NBT], aC1[NBT], aC2[NBT], aC3[NBT];
#pragma unroll
            for (int b = 0; b < NBT; b++) { aC0[b]=0ull; aC1[b]=0ull; aC2[b]=0ull; aC3[b]=0ull; }
#pragma unroll
            for (int kc = 0; kc < 8; kc++) {
                const int wix = 8192 + kc * 128 + half * 64 + s;
                ulonglong2 wc0 = wq[       wix];
                ulonglong2 wc1 = wq[1024 + wix];
                ulonglong2 wc2 = wq[2048 + wix];
                ulonglong2 wc3 = wq[3072 + wix];
#pragma unroll
                for (int b = 0; b < NBT; b++) {
                    ulonglong2 h2 = *(const ulonglong2*)(h1_s + b * HSTRIDE + hofs + kc * 4);
                    aC0[b] = ffma2(wc0.x, h2.x, aC0[b]); aC0[b] = ffma2(wc0.y, h2.y, aC0[b]);
                    aC1[b] = ffma2(wc1.x, h2.x, aC1[b]); aC1[b] = ffma2(wc1.y, h2.y, aC1[b]);
                    aC2[b] = ffma2(wc2.x, h2.x, aC2[b]); aC2[b] = ffma2(wc2.y, h2.y, aC2[b]);
                    aC3[b] = ffma2(wc3.x, h2.x, aC3[b]); aC3[b] = ffma2(wc3.y, h2.y, aC3[b]);
                }
            }
#pragma unroll
            for (int b = 0; b < NBT; b++) {
                float s0 = hadd2(aC0[b]); s0 += __shfl_xor_sync(0xffffffffu, s0, 16);
                float s1 = hadd2(aC1[b]); s1 += __shfl_xor_sync(0xffffffffu, s1, 16);
                float s2 = hadd2(aC2[b]); s2 += __shfl_xor_sync(0xffffffffu, s2, 16);
                float s3 = hadd2(aC3[b]); s3 += __shfl_xor_sync(0xffffffffu, s3, 16);
                if (b < 4) { if (!half) { sg0[b]=s0; sg1[b]=s1; sg2[b]=s2; sg3[b]=s3; } }
                else       { if ( half) { sg0[b-4]=s0; sg1[b-4]=s1; sg2[b-4]=s2; sg3[b-4]=s3; } }
            }

            BAR_SYNC(1 + (t & 1), 256);                // G1FULL: g1a(t) ready
            const float* g1a = g1a_s + (t & 1) * G1A_SLOT;

#pragma unroll
            for (int j = 0; j < 4; j++) {
                if (j < nOwn) {
                    int b  = bo + j;
                    int gi = b * NGATE + s;
                    float p0 = sg0[j] + g1a[gi];
                    float p1 = sg1[j] + g1a[gi + 64];
                    float p2 = sg2[j] + g1a[gi + 128];
                    float p3 = sg3[j] + g1a[gi + 192];
                    float ii = sig_apx(p0), ff = sig_apx(p1), gv = tanh_apx(p2), oo = sig_apx(p3);
                    cS[j] = ff * cS[j] + ii * gv;
                    h1_s[b * HSTRIDE + s + pads] = oo * tanh_apx(cS[j]);
                }
            }

            if (t < T_STEPS - 2) BAR_ARRIVE(3 + (t & 1), 256);  // G1EMPTY
            if (t < T_STEPS - 1) BAR_SYNC(6, 128);              // h1(t) visible
        }
    }
    __syncthreads();

    // ---- output FC: h0 final in slot (T_STEPS-1)&1 = 1 ----
    if (tid < 2 * NBT) {
        int b = (tid < NBT) ? tid : tid - NBT;
        const float* hp = (tid < NBT) ? (h0_s + ((T_STEPS - 1) & 1) * H0_SLOT) : h1_s;
        float sAcc = b_fc[0];
#pragma unroll
        for (int uu = 0; uu < 64; uu++)
            sAcc = fmaf(hp[b * HSTRIDE + uu + ((uu >> 5) << 2)], wfc_s[uu], sAcc);
        out[(tid < NBT ? 0 : B_TOTAL) + bbase + b] = sAcc;
    }
}

__global__ void __launch_bounds__(NTHREADS, 1)
lstm2_kernel(const float* __restrict__ x,
             const float* __restrict__ W_ih0, const float* __restrict__ W_hh0,
             const float* __restrict__ b_ih0, const float* __restrict__ b_hh0,
             const float* __restrict__ W_ih1, const float* __restrict__ W_hh1,
             const float* __restrict__ b_ih1, const float* __restrict__ b_hh1,
             const float* __restrict__ W_fc,  const float* __restrict__ b_fc,
             float* __restrict__ out)
{
    extern __shared__ char smem[];
    ulonglong2* wq = (ulonglong2*)(smem + SM_W);
    float* g1a_s = (float*)(smem + SM_G1A);
    float* h0_s  = (float*)(smem + SM_H0);
    float* h1_s  = (float*)(smem + SM_H1);
    float* wfc_s = (float*)(smem + SM_WFC);

    const int tid = threadIdx.x;

    for (int idx = tid; idx < 4096; idx += NTHREADS) {
        int row = idx >> 4, q = idx & 15;
        int hh = q >> 3, kc = q & 7;
        int d = (row >> 6) * 1024 + kc * 128 + hh * 64 + (row & 63);
        wq[d]        = ((const ulonglong2*)W_hh0)[idx];
        wq[4096 + d] = ((const ulonglong2*)W_ih1)[idx];
        wq[8192 + d] = ((const ulonglong2*)W_hh1)[idx];
    }
    if (tid < 64) wfc_s[tid] = W_fc[tid];

    if (blockIdx.x < NCTA7) {
        lstm_body<7>(blockIdx.x * 7, x, W_ih0, b_ih0, b_hh0, b_ih1, b_hh1,
                     b_fc, out, wq, g1a_s, h0_s, h1_s, wfc_s);
    } else {
        lstm_body<6>(NCTA7 * 7 + (blockIdx.x - NCTA7) * 6, x, W_ih0, b_ih0, b_hh0,
                     b_ih1, b_hh1, b_fc, out, wq, g1a_s, h0_s, h1_s, wfc_s);
    }
}

extern "C" void kernel_launch(void* const* d_in, const int* in_sizes, int n_in,
                              void* d_out, int out_size) {
    const float* x     = (const float*)d_in[0];
    const float* W_ih0 = (const float*)d_in[1];
    const float* W_hh0 = (const float*)d_in[2];
    const float* b_ih0 = (const float*)d_in[3];
    const float* b_hh0 = (const float*)d_in[4];
    const float* W_ih1 = (const float*)d_in[5];
    const float* W_hh1 = (const float*)d_in[6];
    const float* b_ih1 = (const float*)d_in[7];
    const float* b_hh1 = (const float*)d_in[8];
    const float* W_fc  = (const float*)d_in[9];
    const float* b_fc  = (const float*)d_in[10];
    float* out = (float*)d_out;

    cudaFuncSetAttribute(lstm2_kernel,
                         cudaFuncAttributeMaxDynamicSharedMemorySize, SMEM_BYTES);
    lstm2_kernel<<<NCTA, NTHREADS, SMEM_BYTES>>>(
        x, W_ih0, W_hh0, b_ih0, b_hh0,
        W_ih1, W_hh1, b_ih1, b_hh1, W_fc, b_fc, out);
}

// round 15
// speedup vs baseline: 1.0204x; 1.0092x over previous
#include <cuda_runtime.h>

#define B_TOTAL   1024
#define T_STEPS   512
#define NGATE     256
#define NCTA      148
#define NCTA7     136      /* 136 CTAs * 7 + 12 CTAs * 6 = 1024 */
#define NTHREADS  384
#define HSTRIDE   68

typedef unsigned long long u64;

__device__ __forceinline__ u64 ffma2(u64 a, u64 b, u64 c) {
    u64 d;
    asm("fma.rn.f32x2 %0, %1, %2, %3;" : "=l"(d) : "l"(a), "l"(b), "l"(c));
    return d;
}
__device__ __forceinline__ float hadd2(u64 v) {
    float lo, hi;
    asm("mov.b64 {%0, %1}, %2;" : "=f"(lo), "=f"(hi) : "l"(v));
    return lo + hi;
}
__device__ __forceinline__ float tanh_apx(float x) {
    float y;
    asm("tanh.approx.f32 %0, %1;" : "=f"(y) : "f"(x));
    return y;
}
__device__ __forceinline__ float sig_apx(float x) {
    return fmaf(0.5f, tanh_apx(0.5f * x), 0.5f);
}

#define BAR_SYNC(id, cnt)   asm volatile("bar.sync %0, %1;"   :: "r"(id), "r"(cnt) : "memory")
#define BAR_ARRIVE(id, cnt) asm volatile("bar.arrive %0, %1;" :: "r"(id), "r"(cnt) : "memory")
// barrier ids: 0 = __syncthreads, 1/2 = FULL[slot], 3/4 = EMPTY[slot],
//              5 = alpha-internal (256), 6 = beta-internal (128)

// SMEM (bytes), sized for NB=7:
//  wq    [0, 196608): quads. A=whh0 [0,4096), B=wih1 [4096,8192), C=whh1 [8192,12288)
//        A/B sublayout: [rowhi][kc][half][row&127]   conflict-free
//        C   sublayout: [row>>6][kc][half][row&63]   conflict-free
//  g0    [196608): f32 [7 b][256 g]
//  g1a   [203776): f32 ring, 2 slots x [7 b][256 g]  (alpha partial, includes b1)
//  g1b   [218112): f32 [7 b][256 g]                  (beta partial)
//  h0    [225280): f32 [7 b][68]   half0 @ +0, half1 @ +36 floats
//  h1    [227200)
//  wfc   [229120): f32 [64]
#define SM_W      0
#define SM_G0     196608
#define SM_G1A    203776
#define SM_G1B    218112
#define SM_H0     225280
#define SM_H1     227200
#define SM_WFC    229120
#define SMEM_BYTES 229376
#define G1A_SLOT  1792     /* floats per ring slot */

template<int NBT>
__device__ __forceinline__ void lstm_body(
    int bbase, const float* __restrict__ x,
    const float* __restrict__ W_ih0,
    const float* __restrict__ b_ih0, const float* __restrict__ b_hh0,
    const float* __restrict__ b_ih1, const float* __restrict__ b_hh1,
    const float* __restrict__ b_fc, float* __restrict__ out,
    ulonglong2* wq, float* g0_s, float* g1a_s, float* g1b_s,
    float* h0_s, float* h1_s, float* wfc_s)
{
    const int tid  = threadIdx.x;
    const int lane = tid & 31;
    const int half = lane >> 4;
    const int hofs = half * 36;
    const int wid  = tid >> 5;

    for (int i = tid; i < NBT * HSTRIDE; i += NTHREADS) { h0_s[i] = 0.0f; h1_s[i] = 0.0f; }
    __syncthreads();   // weights + zeros visible to all

    if (tid < 256) {
        // ================= ALPHA: whh0 + wih1 on h0 ; act0 =================
        const int sl    = (wid & 7) * 16 + (lane & 15);
        const int wofsA = half * 128 + sl;
        const int myrow = sl + half * 128;
        const float b0v = b_ih0[myrow] + b_hh0[myrow];
        const float b1v = b_ih1[myrow] + b_hh1[myrow];

        const int uA  = tid & 63;
        const int bA0 = tid >> 6;                 // 0..3
        const int bA1 = 4 + bA0;
        const bool hasA1 = (tid < (NBT - 4) * 64);
        const int pad = (uA >> 5) << 2;
        const int gi0 = bA0 * NGATE + uA, hs0 = bA0 * HSTRIDE + uA + pad;
        const int gi1 = bA1 * NGATE + uA, hs1 = bA1 * HSTRIDE + uA + pad;
        const float* xr0 = x + (size_t)(bbase + bA0) * T_STEPS;
        const float* xr1 = x + (size_t)(bbase + bA1) * T_STEPS;
        const float wxi = W_ih0[uA];
        const float wxf = W_ih0[64 + uA];
        const float wxg = W_ih0[128 + uA];
        const float wxo = W_ih0[192 + uA];
        float cA0 = 0.0f, cA1 = 0.0f;

        auto actL0 = [&](int gi, int hs, float& c, float xv) {
            float q0 = fmaf(wxi, xv, g0_s[gi]);
            float q1 = fmaf(wxf, xv, g0_s[gi + 64]);
            float q2 = fmaf(wxg, xv, g0_s[gi + 128]);
            float q3 = fmaf(wxo, xv, g0_s[gi + 192]);
            float ii = sig_apx(q0), ff = sig_apx(q1), gv = tanh_apx(q2), oo = sig_apx(q3);
            c = ff * c + ii * gv;
            h0_s[hs] = oo * tanh_apx(c);
        };

        // prologue: g0(0) = b0 ; act0(0)
#pragma unroll
        for (int b = 0; b < NBT; b++) g0_s[b * NGATE + myrow] = b0v;
        BAR_SYNC(5, 256);
        actL0(gi0, hs0, cA0, __ldg(xr0));
        if (hasA1) actL0(gi1, hs1, cA1, __ldg(xr1));
        BAR_SYNC(5, 256);

        for (int t = 0; t < T_STEPS; t++) {
            if (t >= 2) BAR_SYNC(3 + (t & 1), 384);      // EMPTY: slot reusable
            float* g1a = g1a_s + (t & 1) * G1A_SLOT;

            u64 aA0[NBT], aA1[NBT], aB0[NBT], aB1[NBT];
#pragma unroll
            for (int b = 0; b < NBT; b++) { aA0[b]=0ull; aA1[b]=0ull; aB0[b]=0ull; aB1[b]=0ull; }
#pragma unroll
            for (int kc = 0; kc < 8; kc++) {
                ulonglong2 wa0 = wq[       kc * 256 + wofsA];
                ulonglong2 wa1 = wq[2048 + kc * 256 + wofsA];
                ulonglong2 wb0 = wq[4096 + kc * 256 + wofsA];
                ulonglong2 wb1 = wq[6144 + kc * 256 + wofsA];
#pragma unroll
                for (int b = 0; b < NBT; b++) {
                    ulonglong2 h2 = *(const ulonglong2*)(h0_s + b * HSTRIDE + hofs + kc * 4);
                    aA0[b] = ffma2(wa0.x, h2.x, aA0[b]); aA0[b] = ffma2(wa0.y, h2.y, aA0[b]);
                    aA1[b] = ffma2(wa1.x, h2.x, aA1[b]); aA1[b] = ffma2(wa1.y, h2.y, aA1[b]);
                    aB0[b] = ffma2(wb0.x, h2.x, aB0[b]); aB0[b] = ffma2(wb0.y, h2.y, aB0[b]);
                    aB1[b] = ffma2(wb1.x, h2.x, aB1[b]); aB1[b] = ffma2(wb1.y, h2.y, aB1[b]);
                }
            }
            // single-shfl cross-half reduction: each lane receives only the
            // missing partial of the row it stores (myrow); sends partner's.
#pragma unroll
            for (int b = 0; b < NBT; b++) {
                float fa0 = hadd2(aA0[b]), fa1 = hadd2(aA1[b]);
                float fb0 = hadd2(aB0[b]), fb1 = hadd2(aB1[b]);
                float sendA = half ? fa0 : fa1;
                float sendB = half ? fb0 : fb1;
                float recvA = __shfl_xor_sync(0xffffffffu, sendA, 16);
                float recvB = __shfl_xor_sync(0xffffffffu, sendB, 16);
                float ownA  = half ? fa1 : fa0;
                float ownB  = half ? fb1 : fb0;
                g0_s[b * NGATE + myrow] = ownA + recvA + b0v;   // g0(t+1)
                g1a [b * NGATE + myrow] = ownB + recvB + b1v;   // g1a(t)
            }
            BAR_SYNC(5, 256);                 // drain stores (alpha-wide)
            BAR_ARRIVE(1 + (t & 1), 384);     // FULL: g1a(t) published to beta

            if (t < T_STEPS - 1) {            // act0(t+1)
                float xv0 = __ldg(xr0 + t + 1);
                actL0(gi0, hs0, cA0, xv0);
                if (hasA1) {
                    float xv1 = __ldg(xr1 + t + 1);
                    actL0(gi1, hs1, cA1, xv1);
                }
            }
            BAR_SYNC(5, 256);                 // h0(t+1) visible for next mv
        }
    } else {
        // ================= BETA: whh1 on h1 ; act1 =================
        const int sb    = (wid - 8) * 16 + (lane & 15);
        const int wofsC = half * 64 + sb;
        const int rX    = sb + 64 * (half * 2);
        const int rY    = rX + 64;

        const int btid = tid - 256;
        const int uB   = btid & 63;
        const int pad  = (uB >> 5) << 2;
        const int bB   = btid >> 6;           // 0 or 1
        float cB0 = 0.0f, cB1 = 0.0f, cB2 = 0.0f, cB3 = 0.0f;
        const bool hasJ3 = (NBT == 7) && (btid < 64);

        auto actL1 = [&](const float* g1a, int b, float& c) {
            int gi = b * NGATE + uB;
            float p0 = g1a[gi]       + g1b_s[gi];
            float p1 = g1a[gi + 64]  + g1b_s[gi + 64];
            float p2 = g1a[gi + 128] + g1b_s[gi + 128];
            float p3 = g1a[gi + 192] + g1b_s[gi + 192];
            float ii = sig_apx(p0), ff = sig_apx(p1), gv = tanh_apx(p2), oo = sig_apx(p3);
            c = ff * c + ii * gv;
            h1_s[b * HSTRIDE + uB + pad] = oo * tanh_apx(c);
        };

        for (int t = 0; t < T_STEPS; t++) {
            u64 aC0[NBT], aC1[NBT], aC2[NBT], aC3[NBT];
#pragma unroll
            for (int b = 0; b < NBT; b++) { aC0[b]=0ull; aC1[b]=0ull; aC2[b]=0ull; aC3[b]=0ull; }
#pragma unroll
            for (int kc = 0; kc < 8; kc++) {
                ulonglong2 wc0 = wq[8192        + kc * 128 + wofsC];
                ulonglong2 wc1 = wq[8192 + 1024 + kc * 128 + wofsC];
                ulonglong2 wc2 = wq[8192 + 2048 + kc * 128 + wofsC];
                ulonglong2 wc3 = wq[8192 + 3072 + kc * 128 + wofsC];
#pragma unroll
                for (int b = 0; b < NBT; b++) {
                    ulonglong2 h2 = *(const ulonglong2*)(h1_s + b * HSTRIDE + hofs + kc * 4);
                    aC0[b] = ffma2(wc0.x, h2.x, aC0[b]); aC0[b] = ffma2(wc0.y, h2.y, aC0[b]);
                    aC1[b] = ffma2(wc1.x, h2.x, aC1[b]); aC1[b] = ffma2(wc1.y, h2.y, aC1[b]);
                    aC2[b] = ffma2(wc2.x, h2.x, aC2[b]); aC2[b] = ffma2(wc2.y, h2.y, aC2[b]);
                    aC3[b] = ffma2(wc3.x, h2.x, aC3[b]); aC3[b] = ffma2(wc3.y, h2.y, aC3[b]);
                }
            }
            // single-shfl: half0 stores rows C0(rX),C1(rY); half1 stores C2(rX),C3(rY).
            // pairs (C0,C2) and (C1,C3): send partner's row partial, keep own.
#pragma unroll
            for (int b = 0; b < NBT; b++) {
                float fc0 = hadd2(aC0[b]), fc1 = hadd2(aC1[b]);
                float fc2 = hadd2(aC2[b]), fc3 = hadd2(aC3[b]);
                float sendX = half ? fc0 : fc2;
                float sendY = half ? fc1 : fc3;
                float recvX = __shfl_xor_sync(0xffffffffu, sendX, 16);
                float recvY = __shfl_xor_sync(0xffffffffu, sendY, 16);
                g1b_s[b * NGATE + rX] = (half ? fc2 : fc0) + recvX;
                g1b_s[b * NGATE + rY] = (half ? fc3 : fc1) + recvY;
            }
            BAR_SYNC(6, 128);                 // g1b drained (beta-wide)
            BAR_SYNC(1 + (t & 1), 384);       // FULL: wait g1a(t) from alpha
            const float* g1a = g1a_s + (t & 1) * G1A_SLOT;

            actL1(g1a, bB,     cB0);          // act1(t)
            actL1(g1a, bB + 2, cB1);
            actL1(g1a, bB + 4, cB2);
            if (hasJ3) actL1(g1a, bB + 6, cB3);

            BAR_ARRIVE(3 + (t & 1), 384);     // EMPTY: g1a slot consumed
            BAR_SYNC(6, 128);                 // h1(t) visible for next mv
        }
    }
    __syncthreads();

    // ---- output FC ----
    if (tid < 2 * NBT) {
        int b = (tid < NBT) ? tid : tid - NBT;
        const float* hp = (tid < NBT) ? h0_s : h1_s;
        float s = b_fc[0];
#pragma unroll
        for (int uu = 0; uu < 64; uu++)
            s = fmaf(hp[b * HSTRIDE + uu + ((uu >> 5) << 2)], wfc_s[uu], s);
        out[(tid < NBT ? 0 : B_TOTAL) + bbase + b] = s;
    }
}

__global__ void __launch_bounds__(NTHREADS, 1)
lstm2_kernel(const float* __restrict__ x,
             const float* __restrict__ W_ih0, const float* __restrict__ W_hh0,
             const float* __restrict__ b_ih0, const float* __restrict__ b_hh0,
             const float* __restrict__ W_ih1, const float* __restrict__ W_hh1,
             const float* __restrict__ b_ih1, const float* __restrict__ b_hh1,
             const float* __restrict__ W_fc,  const float* __restrict__ b_fc,
             float* __restrict__ out)
{
    extern __shared__ char smem[];
    ulonglong2* wq = (ulonglong2*)(smem + SM_W);
    float* g0_s  = (float*)(smem + SM_G0);
    float* g1a_s = (float*)(smem + SM_G1A);
    float* g1b_s = (float*)(smem + SM_G1B);
    float* h0_s  = (float*)(smem + SM_H0);
    float* h1_s  = (float*)(smem + SM_H1);
    float* wfc_s = (float*)(smem + SM_WFC);

    const int tid = threadIdx.x;

    // ---- upload weights into conflict-free quad layouts ----
    for (int idx = tid; idx < 4096; idx += NTHREADS) {
        int row = idx >> 4, q = idx & 15;
        int hh = q >> 3, kc = q & 7;
        int dA = (row >> 7) * 2048 + kc * 256 + hh * 128 + (row & 127);
        wq[dA]        = ((const ulonglong2*)W_hh0)[idx];
        wq[4096 + dA] = ((const ulonglong2*)W_ih1)[idx];
        int dC = 8192 + (row >> 6) * 1024 + kc * 128 + hh * 64 + (row & 63);
        wq[dC] = ((const ulonglong2*)W_hh1)[idx];
    }
    if (tid < 64) wfc_s[tid] = W_fc[tid];

    if (blockIdx.x < NCTA7) {
        lstm_body<7>(blockIdx.x * 7, x, W_ih0, b_ih0, b_hh0, b_ih1, b_hh1,
                     b_fc, out, wq, g0_s, g1a_s, g1b_s, h0_s, h1_s, wfc_s);
    } else {
        lstm_body<6>(NCTA7 * 7 + (blockIdx.x - NCTA7) * 6, x, W_ih0, b_ih0, b_hh0,
                     b_ih1, b_hh1, b_fc, out, wq, g0_s, g1a_s, g1b_s, h0_s, h1_s, wfc_s);
    }
}

extern "C" void kernel_launch(void* const* d_in, const int* in_sizes, int n_in,
                              void* d_out, int out_size) {
    const float* x     = (const float*)d_in[0];
    const float* W_ih0 = (const float*)d_in[1];
    const float* W_hh0 = (const float*)d_in[2];
    const float* b_ih0 = (const float*)d_in[3];
    const float* b_hh0 = (const float*)d_in[4];
    const float* W_ih1 = (const float*)d_in[5];
    const float* W_hh1 = (const float*)d_in[6];
    const float* b_ih1 = (const float*)d_in[7];
    const float* b_hh1 = (const float*)d_in[8];
    const float* W_fc  = (const float*)d_in[9];
    const float* b_fc  = (const float*)d_in[10];
    float* out = (float*)d_out;

    cudaFuncSetAttribute(lstm2_kernel,
                         cudaFuncAttributeMaxDynamicSharedMemorySize, SMEM_BYTES);
    lstm2_kernel<<<NCTA, NTHREADS, SMEM_BYTES>>>(
        x, W_ih0, W_hh0, b_ih0, b_hh0,
        W_ih1, W_hh1, b_ih1, b_hh1, W_fc, b_fc, out);
}

// round 16
// speedup vs baseline: 1.0376x; 1.0168x over previous
#include <cuda_runtime.h>

#define B_TOTAL   1024
#define T_STEPS   512
#define NGATE     256
#define NCTA      148
#define NCTA7     136      /* 136 CTAs * 7 + 12 CTAs * 6 = 1024 */
#define NTHREADS  384
#define HSTRIDE   68

typedef unsigned long long u64;

__device__ __forceinline__ u64 ffma2(u64 a, u64 b, u64 c) {
    u64 d;
    asm("fma.rn.f32x2 %0, %1, %2, %3;" : "=l"(d) : "l"(a), "l"(b), "l"(c));
    return d;
}
__device__ __forceinline__ float hadd2(u64 v) {
    float lo, hi;
    asm("mov.b64 {%0, %1}, %2;" : "=f"(lo), "=f"(hi) : "l"(v));
    return lo + hi;
}
__device__ __forceinline__ float tanh_apx(float x) {
    float y;
    asm("tanh.approx.f32 %0, %1;" : "=f"(y) : "f"(x));
    return y;
}
__device__ __forceinline__ float sig_apx(float x) {
    return fmaf(0.5f, tanh_apx(0.5f * x), 0.5f);
}

#define BAR_SYNC(id, cnt)   asm volatile("bar.sync %0, %1;"   :: "r"(id), "r"(cnt) : "memory")
#define BAR_ARRIVE(id, cnt) asm volatile("bar.arrive %0, %1;" :: "r"(id), "r"(cnt) : "memory")
// barrier ids: 0 = __syncthreads, 1/2 = FULL[slot], 3/4 = EMPTY[slot],
//              5 = alpha-internal (256), 6 = beta-internal (128)

// SMEM (bytes), sized for NB=7:
//  wq    [0, 196608): quads. A=whh0 [0,4096), B=wih1 [4096,8192), C=whh1 [8192,12288)
//        A/B sublayout: [rowhi][kc][half][row&127]   conflict-free
//        C   sublayout: [row>>6][kc][half][row&63]   conflict-free
//  g0    [196608): f32 [7 b][256 g]
//  g1a   [203776): f32 ring, 2 slots x [7 b][256 g]  (alpha partial, includes b1)
//  g1b   [218112): f32 [7 b][256 g]                  (beta partial)
//  h0    [225280): f32 [7 b][68]   half0 @ +0, half1 @ +36 floats
//  h1    [227200)
//  wfc   [229120): f32 [64]
#define SM_W      0
#define SM_G0     196608
#define SM_G1A    203776
#define SM_G1B    218112
#define SM_H0     225280
#define SM_H1     227200
#define SM_WFC    229120
#define SMEM_BYTES 229376
#define G1A_SLOT  1792     /* floats per ring slot */

template<int NBT>
__device__ __forceinline__ void lstm_body(
    int bbase, const float* __restrict__ x,
    const float* __restrict__ W_ih0,
    const float* __restrict__ b_ih0, const float* __restrict__ b_hh0,
    const float* __restrict__ b_ih1, const float* __restrict__ b_hh1,
    const float* __restrict__ b_fc, float* __restrict__ out,
    ulonglong2* wq, float* g0_s, float* g1a_s, float* g1b_s,
    float* h0_s, float* h1_s, float* wfc_s)
{
    const int tid  = threadIdx.x;
    const int lane = tid & 31;
    const int half = lane >> 4;
    const int hofs = half * 36;
    const int wid  = tid >> 5;

    for (int i = tid; i < NBT * HSTRIDE; i += NTHREADS) { h0_s[i] = 0.0f; h1_s[i] = 0.0f; }
    __syncthreads();   // weights + zeros visible to all

    if (tid < 256) {
        // ================= ALPHA: whh0 + wih1 on h0 ; act0 =================
        const int sl    = (wid & 7) * 16 + (lane & 15);
        const int wofsA = half * 128 + sl;
        const int myrow = sl + half * 128;
        // positional rowhi blocks: own = this lane's stored row, oth = partner's
        const int oOwn = half ? 2048 : 0;
        const int oOth = 2048 - oOwn;
        const float b0v = b_ih0[myrow] + b_hh0[myrow];
        const float b1v = b_ih1[myrow] + b_hh1[myrow];

        const int uA  = tid & 63;
        const int bA0 = tid >> 6;                 // 0..3
        const int bA1 = 4 + bA0;
        const bool hasA1 = (tid < (NBT - 4) * 64);
        const int pad = (uA >> 5) << 2;
        const int gi0 = bA0 * NGATE + uA, hs0 = bA0 * HSTRIDE + uA + pad;
        const int gi1 = bA1 * NGATE + uA, hs1 = bA1 * HSTRIDE + uA + pad;
        const float* xr0 = x + (size_t)(bbase + bA0) * T_STEPS;
        const float* xr1 = x + (size_t)(bbase + bA1) * T_STEPS;
        const float wxi = W_ih0[uA];
        const float wxf = W_ih0[64 + uA];
        const float wxg = W_ih0[128 + uA];
        const float wxo = W_ih0[192 + uA];
        float cA0 = 0.0f, cA1 = 0.0f;

        auto actL0 = [&](int gi, int hs, float& c, float xv) {
            float q0 = fmaf(wxi, xv, g0_s[gi]);
            float q1 = fmaf(wxf, xv, g0_s[gi + 64]);
            float q2 = fmaf(wxg, xv, g0_s[gi + 128]);
            float q3 = fmaf(wxo, xv, g0_s[gi + 192]);
            float ii = sig_apx(q0), ff = sig_apx(q1), gv = tanh_apx(q2), oo = sig_apx(q3);
            c = ff * c + ii * gv;
            h0_s[hs] = oo * tanh_apx(c);
        };

        // prologue: g0(0) = b0 ; act0(0)
#pragma unroll
        for (int b = 0; b < NBT; b++) g0_s[b * NGATE + myrow] = b0v;
        BAR_SYNC(5, 256);
        actL0(gi0, hs0, cA0, __ldg(xr0));
        if (hasA1) actL0(gi1, hs1, cA1, __ldg(xr1));
        BAR_SYNC(5, 256);

        for (int t = 0; t < T_STEPS; t++) {
            if (t >= 2) BAR_SYNC(3 + (t & 1), 384);      // EMPTY: slot reusable
            float* g1a = g1a_s + (t & 1) * G1A_SLOT;

            u64 aAown[NBT], aAoth[NBT], aBown[NBT], aBoth[NBT];
#pragma unroll
            for (int b = 0; b < NBT; b++) { aAown[b]=0ull; aAoth[b]=0ull; aBown[b]=0ull; aBoth[b]=0ull; }
#pragma unroll
            for (int kc = 0; kc < 8; kc++) {
                ulonglong2 waOwn = wq[oOwn        + kc * 256 + wofsA];
                ulonglong2 waOth = wq[oOth        + kc * 256 + wofsA];
                ulonglong2 wbOwn = wq[4096 + oOwn + kc * 256 + wofsA];
                ulonglong2 wbOth = wq[4096 + oOth + kc * 256 + wofsA];
#pragma unroll
                for (int b = 0; b < NBT; b++) {
                    ulonglong2 h2 = *(const ulonglong2*)(h0_s + b * HSTRIDE + hofs + kc * 4);
                    aAown[b] = ffma2(waOwn.x, h2.x, aAown[b]); aAown[b] = ffma2(waOwn.y, h2.y, aAown[b]);
                    aAoth[b] = ffma2(waOth.x, h2.x, aAoth[b]); aAoth[b] = ffma2(waOth.y, h2.y, aAoth[b]);
                    aBown[b] = ffma2(wbOwn.x, h2.x, aBown[b]); aBown[b] = ffma2(wbOwn.y, h2.y, aBown[b]);
                    aBoth[b] = ffma2(wbOth.x, h2.x, aBoth[b]); aBoth[b] = ffma2(wbOth.y, h2.y, aBoth[b]);
                }
            }
            // branchless single-shfl cross-half reduction
#pragma unroll
            for (int b = 0; b < NBT; b++) {
                float sendA = hadd2(aAoth[b]);
                float sendB = hadd2(aBoth[b]);
                float recvA = __shfl_xor_sync(0xffffffffu, sendA, 16);
                float recvB = __shfl_xor_sync(0xffffffffu, sendB, 16);
                g0_s[b * NGATE + myrow] = hadd2(aAown[b]) + recvA + b0v;   // g0(t+1)
                g1a [b * NGATE + myrow] = hadd2(aBown[b]) + recvB + b1v;   // g1a(t)
            }
            BAR_SYNC(5, 256);                 // drain stores (alpha-wide)
            BAR_ARRIVE(1 + (t & 1), 384);     // FULL: g1a(t) published to beta

            if (t < T_STEPS - 1) {            // act0(t+1)
                float xv0 = __ldg(xr0 + t + 1);
                actL0(gi0, hs0, cA0, xv0);
                if (hasA1) {
                    float xv1 = __ldg(xr1 + t + 1);
                    actL0(gi1, hs1, cA1, xv1);
                }
            }
            BAR_SYNC(5, 256);                 // h0(t+1) visible for next mv
        }
    } else {
        // ================= BETA: whh1 on h1 ; act1 =================
        const int sb    = (wid - 8) * 16 + (lane & 15);
        const int wofsC = half * 64 + sb;
        const int rX    = sb + 64 * (half * 2);
        const int rY    = rX + 64;
        // positional pair-blocks: own rows = {rX, rY}, other = partner's pair
        const int oOwnC = half ? 2048 : 0;     // block index (quads): rows {sb+128,sb+192} vs {sb,sb+64}
        const int oOthC = 2048 - oOwnC;

        const int btid = tid - 256;
        const int uB   = btid & 63;
        const int pad  = (uB >> 5) << 2;
        const int bB   = btid >> 6;           // 0 or 1
        float cB0 = 0.0f, cB1 = 0.0f, cB2 = 0.0f, cB3 = 0.0f;
        const bool hasJ3 = (NBT == 7) && (btid < 64);

        auto actL1 = [&](const float* g1a, int b, float& c) {
            int gi = b * NGATE + uB;
            float p0 = g1a[gi]       + g1b_s[gi];
            float p1 = g1a[gi + 64]  + g1b_s[gi + 64];
            float p2 = g1a[gi + 128] + g1b_s[gi + 128];
            float p3 = g1a[gi + 192] + g1b_s[gi + 192];
            float ii = sig_apx(p0), ff = sig_apx(p1), gv = tanh_apx(p2), oo = sig_apx(p3);
            c = ff * c + ii * gv;
            h1_s[b * HSTRIDE + uB + pad] = oo * tanh_apx(c);
        };

        for (int t = 0; t < T_STEPS; t++) {
            u64 aOwnX[NBT], aOwnY[NBT], aOthX[NBT], aOthY[NBT];
#pragma unroll
            for (int b = 0; b < NBT; b++) { aOwnX[b]=0ull; aOwnY[b]=0ull; aOthX[b]=0ull; aOthY[b]=0ull; }
#pragma unroll
            for (int kc = 0; kc < 8; kc++) {
                ulonglong2 wOwnX = wq[8192 + oOwnC        + kc * 128 + wofsC];
                ulonglong2 wOwnY = wq[8192 + oOwnC + 1024 + kc * 128 + wofsC];
                ulonglong2 wOthX = wq[8192 + oOthC        + kc * 128 + wofsC];
                ulonglong2 wOthY = wq[8192 + oOthC + 1024 + kc * 128 + wofsC];
#pragma unroll
                for (int b = 0; b < NBT; b++) {
                    ulonglong2 h2 = *(const ulonglong2*)(h1_s + b * HSTRIDE + hofs + kc * 4);
                    aOwnX[b] = ffma2(wOwnX.x, h2.x, aOwnX[b]); aOwnX[b] = ffma2(wOwnX.y, h2.y, aOwnX[b]);
                    aOwnY[b] = ffma2(wOwnY.x, h2.x, aOwnY[b]); aOwnY[b] = ffma2(wOwnY.y, h2.y, aOwnY[b]);
                    aOthX[b] = ffma2(wOthX.x, h2.x, aOthX[b]); aOthX[b] = ffma2(wOthX.y, h2.y, aOthX[b]);
                    aOthY[b] = ffma2(wOthY.x, h2.x, aOthY[b]); aOthY[b] = ffma2(wOthY.y, h2.y, aOthY[b]);
                }
            }
            // branchless single-shfl reduction
#pragma unroll
            for (int b = 0; b < NBT; b++) {
                float sendX = hadd2(aOthX[b]);
                float sendY = hadd2(aOthY[b]);
                float recvX = __shfl_xor_sync(0xffffffffu, sendX, 16);
                float recvY = __shfl_xor_sync(0xffffffffu, sendY, 16);
                g1b_s[b * NGATE + rX] = hadd2(aOwnX[b]) + recvX;
                g1b_s[b * NGATE + rY] = hadd2(aOwnY[b]) + recvY;
            }
            BAR_SYNC(6, 128);                 // g1b drained (beta-wide)
            BAR_SYNC(1 + (t & 1), 384);       // FULL: wait g1a(t) from alpha
            const float* g1a = g1a_s + (t & 1) * G1A_SLOT;

            actL1(g1a, bB,     cB0);          // act1(t)
            actL1(g1a, bB + 2, cB1);
            actL1(g1a, bB + 4, cB2);
            if (hasJ3) actL1(g1a, bB + 6, cB3);

            BAR_ARRIVE(3 + (t & 1), 384);     // EMPTY: g1a slot consumed
            BAR_SYNC(6, 128);                 // h1(t) visible for next mv
        }
    }
    __syncthreads();

    // ---- output FC ----
    if (tid < 2 * NBT) {
        int b = (tid < NBT) ? tid : tid - NBT;
        const float* hp = (tid < NBT) ? h0_s : h1_s;
        float s = b_fc[0];
#pragma unroll
        for (int uu = 0; uu < 64; uu++)
            s = fmaf(hp[b * HSTRIDE + uu + ((uu >> 5) << 2)], wfc_s[uu], s);
        out[(tid < NBT ? 0 : B_TOTAL) + bbase + b] = s;
    }
}

__global__ void __launch_bounds__(NTHREADS, 1)
lstm2_kernel(const float* __restrict__ x,
             const float* __restrict__ W_ih0, const float* __restrict__ W_hh0,
             const float* __restrict__ b_ih0, const float* __restrict__ b_hh0,
             const float* __restrict__ W_ih1, const float* __restrict__ W_hh1,
             const float* __restrict__ b_ih1, const float* __restrict__ b_hh1,
             const float* __restrict__ W_fc,  const float* __restrict__ b_fc,
             float* __restrict__ out)
{
    extern __shared__ char smem[];
    ulonglong2* wq = (ulonglong2*)(smem + SM_W);
    float* g0_s  = (float*)(smem + SM_G0);
    float* g1a_s = (float*)(smem + SM_G1A);
    float* g1b_s = (float*)(smem + SM_G1B);
    float* h0_s  = (float*)(smem + SM_H0);
    float* h1_s  = (float*)(smem + SM_H1);
    float* wfc_s = (float*)(smem + SM_WFC);

    const int tid = threadIdx.x;

    // ---- upload weights into conflict-free quad layouts ----
    for (int idx = tid; idx < 4096; idx += NTHREADS) {
        int row = idx >> 4, q = idx & 15;
        int hh = q >> 3, kc = q & 7;
        int dA = (row >> 7) * 2048 + kc * 256 + hh * 128 + (row & 127);
        wq[dA]        = ((const ulonglong2*)W_hh0)[idx];
        wq[4096 + dA] = ((const ulonglong2*)W_ih1)[idx];
        int dC = 8192 + (row >> 6) * 1024 + kc * 128 + hh * 64 + (row & 63);
        wq[dC] = ((const ulonglong2*)W_hh1)[idx];
    }
    if (tid < 64) wfc_s[tid] = W_fc[tid];

    if (blockIdx.x < NCTA7) {
        lstm_body<7>(blockIdx.x * 7, x, W_ih0, b_ih0, b_hh0, b_ih1, b_hh1,
                     b_fc, out, wq, g0_s, g1a_s, g1b_s, h0_s, h1_s, wfc_s);
    } else {
        lstm_body<6>(NCTA7 * 7 + (blockIdx.x - NCTA7) * 6, x, W_ih0, b_ih0, b_hh0,
                     b_ih1, b_hh1, b_fc, out, wq, g0_s, g1a_s, g1b_s, h0_s, h1_s, wfc_s);
    }
}

extern "C" void kernel_launch(void* const* d_in, const int* in_sizes, int n_in,
                              void* d_out, int out_size) {
    const float* x     = (const float*)d_in[0];
    const float* W_ih0 = (const float*)d_in[1];
    const float* W_hh0 = (const float*)d_in[2];
    const float* b_ih0 = (const float*)d_in[3];
    const float* b_hh0 = (const float*)d_in[4];
    const float* W_ih1 = (const float*)d_in[5];
    const float* W_hh1 = (const float*)d_in[6];
    const float* b_ih1 = (const float*)d_in[7];
    const float* b_hh1 = (const float*)d_in[8];
    const float* W_fc  = (const float*)d_in[9];
    const float* b_fc  = (const float*)d_in[10];
    float* out = (float*)d_out;

    cudaFuncSetAttribute(lstm2_kernel,
                         cudaFuncAttributeMaxDynamicSharedMemorySize, SMEM_BYTES);
    lstm2_kernel<<<NCTA, NTHREADS, SMEM_BYTES>>>(
        x, W_ih0, W_hh0, b_ih0, b_hh0,
        W_ih1, W_hh1, b_ih1, b_hh1, W_fc, b_fc, out);
}